// round 16
// baseline (speedup 1.0000x reference)
#include <cuda_runtime.h>
#include <math.h>

// Problem constants (fixed by setup_inputs)
#define B_  32
#define K_  16
#define T_  30
#define N_  128
#define n_  20
#define NN  (N_ * n_)          // 2560 nodes per batch
#define BK  (B_ * K_)          // 512
#define BLOCK 256
#define CHUNK0 64              // phase-A nodes (register-cached)
#define REST   (NN - CHUNK0)   // 2496
#define NSEG   8
#define SEGLEN (REST / NSEG)   // 312

#define YAW_THRESH  1.0471975511965976f   // pi/3
#define INF_F       __int_as_float(0x7f800000)
#define INF_BITS    0x7f800000

__device__ __forceinline__ float fast_sqrt(float x) {
    float r;
    asm("sqrt.approx.f32 %0, %1;" : "=f"(r) : "f"(x));
    return r;
}

// cost = relu(dist - 2) + relu(|wrap(yaw_n - yaw_p)| - pi/3); masked -> inf.
// yaw = -atan2(dx, dy) reflects the direction angle, so |wrapped yaw diff| ==
// angle(u, v) between raw direction vectors (starts / t = 0 -> dir (0, 1)).
//
// Cheap-cost identities (tan(pi/3)^2 == 3):
//   angle <= pi/3  <=>  dt >= 0 AND cr^2 <= 3*dt^2  ->  cost = relu(dist - 2)
//                                                       (no transcendental)
//   otherwise cost >= relu(dist - 2) = cd           ->  prune when cd >= lmin;
//                                                       atan2 only for nodes
//                                                       that could still win.
// Exact zero: angle-ok AND d2 <= 4; cost >= 0, so any zero finalizes the min.
//
// One block per (b, k), 256 threads = 8 warps:
//  Phase 0: threads 0-63 build s_nd[64] = (x | inf-if-masked, y, ux, uy);
//           threads 64-93 build s_ptv[30]; threads 96-127 init control state.
//  Phase A: warp w handles t = w, w+8, w+16(, w+24). The 64 nodes live in
//           registers (2 x LDS.128, loaded once, reused across its t's):
//           per t ~ 1 broadcast LDS.128 + ~26 flops + 1 ballot.
//           Miss probability ~ 8e-4/task -> ~13 Phase-B items grid-wide.
//  Phase B: unresolved t's flattened into (u, seg) items pulled by all
//           8 warps; cheap-cost pruned scan with zero-break; atomicMin on
//           int-encoded nonnegative costs (bit order == value order, min is
//           order-independent -> deterministic output on every replay).
__global__ __launch_bounds__(BLOCK)
void consistency_kernel(const float* __restrict__ preds,
                        const float* __restrict__ cn,
                        const int*   __restrict__ mask,
                        float* __restrict__ out) {
    const int bk = blockIdx.x;
    const int b  = bk >> 4;                 // / K_

    const float2* cnb = (const float2*)cn + (size_t)b * NN;
    const int*    mb  = mask + (size_t)b * NN;
    const float2* pp  = (const float2*)preds + (size_t)bk * T_;

    __shared__ float4 s_nd[CHUNK0];         // 1 KB
    __shared__ float4 s_ptv[T_];
    __shared__ int    s_minb[32];
    __shared__ int    s_unres[32];
    __shared__ int    s_ucnt;

    const int tid  = threadIdx.x;
    const int warp = tid >> 5;
    const int lane = tid & 31;

    // ---------------- Phase 0 (split across warps) ----------------
    if (tid < CHUNK0) {
        const int idx = tid;
        float2 p = cnb[idx];
        float2 q = cnb[idx > 0 ? idx - 1 : 0];
        int    m = mb[idx];
        bool start = (idx % n_ == 0);
        float ux = start ? 0.0f : p.x - q.x;
        float uy = start ? 1.0f : p.y - q.y;
        float x  = (m == 1) ? INF_F : p.x;   // masked -> d2 = +inf
        s_nd[idx] = make_float4(x, p.y, ux, uy);
    } else if (tid < CHUNK0 + T_) {
        const int r = tid - CHUNK0;
        float2 pt = pp[r];
        float vx = 0.0f, vy = 1.0f;          // yaw 0 <-> direction (0, 1)
        if (r != 0) {
            float2 pm = pp[r - 1];
            vx = pt.x - pm.x;
            vy = pt.y - pm.y;
        }
        s_ptv[r] = make_float4(pt.x, pt.y, vx, vy);
    } else if (tid >= 96 && tid < 128) {
        const int s = tid - 96;
        s_minb[s] = (s < T_) ? INF_BITS : 0;
        if (s == 0) s_ucnt = 0;
    }
    __syncthreads();

    // ---------------- Phase A: 64 nodes in registers, <=4 t's per warp ----
    const float4 nd0 = s_nd[lane];
    const float4 nd1 = s_nd[lane + 32];

    const int nt = (warp < 6) ? 4 : 3;       // t = warp + 8i < 30

    for (int i = 0; i < nt; ++i) {
        const int t = warp + i * 8;
        const float4 ptv = s_ptv[t];

        float d2[2], dt[2], cr[2];
        bool  aok[2];                        // angle <= pi/3
        bool  anyz = false;

#define ZEVAL(j, ND) do {                                                  \
        float dx = (ND).x - ptv.x;                                         \
        float dy = (ND).y - ptv.y;                                         \
        d2[j] = fmaf(dx, dx, dy * dy);                                     \
        dt[j] = fmaf((ND).z, ptv.z, (ND).w * ptv.w);                       \
        cr[j] = fmaf((ND).z, ptv.w, -(ND).w * ptv.z);                      \
        aok[j] = (dt[j] >= 0.0f) && (cr[j] * cr[j] <= 3.0f * dt[j] * dt[j]);\
        anyz |= aok[j] && (d2[j] <= 4.0f);                                 \
    } while (0)

        ZEVAL(0, nd0);
        ZEVAL(1, nd1);
#undef ZEVAL

        if (__ballot_sync(0xffffffffu, anyz)) {
            if (lane == 0) s_minb[t] = 0;
        } else {
            // cheap costs: angle-ok -> cd exactly; else atan2 iff cd < lmin
            float lmin = INF_F;
            #pragma unroll
            for (int j = 0; j < 2; ++j) {
                float cd = (d2[j] <= 4.0f) ? 0.0f : (fast_sqrt(d2[j]) - 2.0f);
                if (aok[j]) {
                    lmin = fminf(lmin, cd);
                } else if (cd < lmin) {
                    float a = atan2f(fabsf(cr[j]), dt[j]);
                    lmin = fminf(lmin, cd + fmaxf(a - YAW_THRESH, 0.0f));
                }
            }
            lmin = fminf(lmin, __shfl_xor_sync(0xffffffffu, lmin, 16));
            lmin = fminf(lmin, __shfl_xor_sync(0xffffffffu, lmin, 8));
            lmin = fminf(lmin, __shfl_xor_sync(0xffffffffu, lmin, 4));
            lmin = fminf(lmin, __shfl_xor_sync(0xffffffffu, lmin, 2));
            lmin = fminf(lmin, __shfl_xor_sync(0xffffffffu, lmin, 1));
            if (lane == 0) {
                s_minb[t] = __float_as_int(lmin);
                int pos = atomicAdd(&s_ucnt, 1);
                s_unres[pos] = t;
            }
        }
    }
    __syncthreads();

    // ---------------- Phase B: flattened straggler segments ---------------
    const int ucnt = s_ucnt;
    if (ucnt > 0) {
        const int nitems = ucnt * NSEG;
        for (int it = warp; it < nitems; it += 8) {
            const int u = it >> 3;
            const int s = it & (NSEG - 1);
            const int t = s_unres[u];
            const float4 ptv = s_ptv[t];

            const int segbase = CHUNK0 + s * SEGLEN;
            float lmin = __int_as_float(s_minb[t]);  // seed with known bound
            for (int off = lane; off < SEGLEN; off += 32) {
                const int idx = segbase + off;
                float2 p = cnb[idx];
                float2 q = cnb[idx - 1];
                int    m = mb[idx];
                bool start = (idx % n_ == 0);
                float ux = start ? 0.0f : p.x - q.x;
                float uy = start ? 1.0f : p.y - q.y;
                float x  = (m == 1) ? INF_F : p.x;

                float dx = x - ptv.x;
                float dy = p.y - ptv.y;
                float d2 = fmaf(dx, dx, dy * dy);
                float dt = fmaf(ux, ptv.z, uy * ptv.w);
                float cr = fmaf(ux, ptv.w, -uy * ptv.z);
                bool aok = (dt >= 0.0f) && (cr * cr <= 3.0f * dt * dt);

                float cd = (d2 <= 4.0f) ? 0.0f : (fast_sqrt(d2) - 2.0f);
                if (aok) {
                    lmin = fminf(lmin, cd);          // cost == cd exactly
                    if (lmin == 0.0f) break;         // global min reached
                } else if (cd < lmin) {              // prune: cost >= cd
                    float a = atan2f(fabsf(cr), dt);
                    lmin = fminf(lmin, cd + fmaxf(a - YAW_THRESH, 0.0f));
                }
            }
            lmin = fminf(lmin, __shfl_xor_sync(0xffffffffu, lmin, 16));
            lmin = fminf(lmin, __shfl_xor_sync(0xffffffffu, lmin, 8));
            lmin = fminf(lmin, __shfl_xor_sync(0xffffffffu, lmin, 4));
            lmin = fminf(lmin, __shfl_xor_sync(0xffffffffu, lmin, 2));
            lmin = fminf(lmin, __shfl_xor_sync(0xffffffffu, lmin, 1));
            // nonneg floats: int-bit order == value order -> deterministic
            if (lane == 0) atomicMin(&s_minb[t], __float_as_int(lmin));
        }
        __syncthreads();
    }

    // ---------------- Sum over T (deterministic shfl tree) ----------------
    if (tid < 32) {
        float v = __int_as_float(s_minb[tid]);   // t >= 30 slots hold 0
        v += __shfl_xor_sync(0xffffffffu, v, 16);
        v += __shfl_xor_sync(0xffffffffu, v, 8);
        v += __shfl_xor_sync(0xffffffffu, v, 4);
        v += __shfl_xor_sync(0xffffffffu, v, 2);
        v += __shfl_xor_sync(0xffffffffu, v, 1);
        if (tid == 0) out[bk] = v;
    }
}

extern "C" void kernel_launch(void* const* d_in, const int* in_sizes, int n_in,
                              void* d_out, int out_size) {
    const float* preds = (const float*)d_in[0];
    const float* cn    = (const float*)d_in[1];
    const int*   mask  = (const int*)d_in[2];
    float* out = (float*)d_out;

    consistency_kernel<<<BK, BLOCK>>>(preds, cn, mask, out);
}

// round 17
// speedup vs baseline: 1.1554x; 1.1554x over previous
#include <cuda_runtime.h>
#include <math.h>

// Problem constants (fixed by setup_inputs)
#define B_  32
#define K_  16
#define T_  30
#define N_  128
#define n_  20
#define NN  (N_ * n_)          // 2560 nodes per batch
#define BK  (B_ * K_)          // 512
#define BLOCK 256
#define CHUNK0 128             // phase-A nodes
#define REST   (NN - CHUNK0)   // 2432
#define NSEG   8
#define SEGLEN (REST / NSEG)   // 304

#define YAW_THRESH  1.0471975511965976f   // pi/3
#define INF_F       __int_as_float(0x7f800000)
#define INF_BITS    0x7f800000

__device__ __forceinline__ float fast_sqrt(float x) {
    float r;
    asm("sqrt.approx.f32 %0, %1;" : "=f"(r) : "f"(x));
    return r;
}

// cost = relu(dist - 2) + relu(|wrap(yaw_n - yaw_p)| - pi/3); masked -> inf.
// yaw = -atan2(dx, dy) reflects the direction angle, so |wrapped yaw diff| ==
// angle(u, v) between raw direction vectors (starts / t = 0 -> dir (0, 1)).
//
// Cheap-cost identities (tan(pi/3)^2 == 3):
//   angle <= pi/3  <=>  dt >= 0 AND cr^2 <= 3*dt^2  ->  cost = relu(dist - 2)
//                                                       (no transcendental)
//   otherwise cost >= relu(dist - 2) = cd           ->  prune when cd >= lmin;
//                                                       atan2 only for nodes
//                                                       that could still win.
// Exact zero: angle-ok AND d2 <= 4; cost >= 0, so any zero finalizes the min.
//
// One block per (b, k), 256 threads = 8 warps:
//  Phase 0: threads 0-127 build s_nd[128] = (x | inf-if-masked, y, ux, uy);
//           threads 128+ build s_ptv[30] = (pt.x, pt.y, vx, vy) and init
//           control state. Node and pred loads issue in the same gmem round.
//  Phase A: warp w handles t = w, w+8, w+16(, w+24). The 128 nodes live in
//           registers (4 x LDS.128, loaded once, reused across all its t's):
//           per t ~ 1 broadcast LDS.128 + ~50 flops + 1 ballot.
//           Miss probability ~ 1e-6/task -> Phase B is vanishingly rare.
//  Phase B: unresolved t's flattened into (u, seg) items pulled by all
//           8 warps; cheap-cost pruned scan with zero-break; atomicMin on
//           int-encoded nonnegative costs (bit order == value order, min is
//           order-independent -> deterministic output on every replay).
__global__ __launch_bounds__(BLOCK)
void consistency_kernel(const float* __restrict__ preds,
                        const float* __restrict__ cn,
                        const int*   __restrict__ mask,
                        float* __restrict__ out) {
    const int bk = blockIdx.x;
    const int b  = bk >> 4;                 // / K_

    const float2* cnb = (const float2*)cn + (size_t)b * NN;
    const int*    mb  = mask + (size_t)b * NN;
    const float2* pp  = (const float2*)preds + (size_t)bk * T_;

    __shared__ float4 s_nd[CHUNK0];         // 2 KB
    __shared__ float4 s_ptv[T_];
    __shared__ int    s_minb[32];
    __shared__ int    s_unres[32];
    __shared__ int    s_ucnt;

    const int tid  = threadIdx.x;
    const int warp = tid >> 5;
    const int lane = tid & 31;

    // ---------------- Phase 0 (split across warps) ----------------
    if (tid < CHUNK0) {
        const int idx = tid;
        float2 p = cnb[idx];
        float2 q = cnb[idx > 0 ? idx - 1 : 0];
        int    m = mb[idx];
        bool start = (idx % n_ == 0);
        float ux = start ? 0.0f : p.x - q.x;
        float uy = start ? 1.0f : p.y - q.y;
        float x  = (m == 1) ? INF_F : p.x;   // masked -> d2 = +inf
        s_nd[idx] = make_float4(x, p.y, ux, uy);
    } else {
        const int r = tid - 128;
        if (r < T_) {
            float2 pt = pp[r];
            float vx = 0.0f, vy = 1.0f;      // yaw 0 <-> direction (0, 1)
            if (r != 0) {
                float2 pm = pp[r - 1];
                vx = pt.x - pm.x;
                vy = pt.y - pm.y;
            }
            s_ptv[r] = make_float4(pt.x, pt.y, vx, vy);
        } else if (r < T_ + 32) {
            const int s = r - T_;            // threads 158..189 -> slots 0..31
            s_minb[s] = (s < T_) ? INF_BITS : 0;
            if (s == 0) s_ucnt = 0;
        }
    }
    __syncthreads();

    // ---------------- Phase A: nodes in registers, <=4 t's per warp -------
    const float4 nd0 = s_nd[lane];
    const float4 nd1 = s_nd[lane + 32];
    const float4 nd2 = s_nd[lane + 64];
    const float4 nd3 = s_nd[lane + 96];

    const int nt = (warp < 6) ? 4 : 3;       // t = warp + 8i < 30

    for (int i = 0; i < nt; ++i) {
        const int t = warp + i * 8;
        const float4 ptv = s_ptv[t];

        float d2[4], dt[4], cr[4];
        bool  aok[4];                        // angle <= pi/3
        bool  anyz = false;

#define ZEVAL(j, ND) do {                                                  \
        float dx = (ND).x - ptv.x;                                         \
        float dy = (ND).y - ptv.y;                                         \
        d2[j] = fmaf(dx, dx, dy * dy);                                     \
        dt[j] = fmaf((ND).z, ptv.z, (ND).w * ptv.w);                       \
        cr[j] = fmaf((ND).z, ptv.w, -(ND).w * ptv.z);                      \
        aok[j] = (dt[j] >= 0.0f) && (cr[j] * cr[j] <= 3.0f * dt[j] * dt[j]);\
        anyz |= aok[j] && (d2[j] <= 4.0f);                                 \
    } while (0)

        ZEVAL(0, nd0);
        ZEVAL(1, nd1);
        ZEVAL(2, nd2);
        ZEVAL(3, nd3);
#undef ZEVAL

        if (__ballot_sync(0xffffffffu, anyz)) {
            if (lane == 0) s_minb[t] = 0;
        } else {
            // cheap costs: angle-ok -> cd exactly; else atan2 iff cd < lmin
            float lmin = INF_F;
            #pragma unroll
            for (int j = 0; j < 4; ++j) {
                float cd = (d2[j] <= 4.0f) ? 0.0f : (fast_sqrt(d2[j]) - 2.0f);
                if (aok[j]) {
                    lmin = fminf(lmin, cd);
                } else if (cd < lmin) {
                    float a = atan2f(fabsf(cr[j]), dt[j]);
                    lmin = fminf(lmin, cd + fmaxf(a - YAW_THRESH, 0.0f));
                }
            }
            lmin = fminf(lmin, __shfl_xor_sync(0xffffffffu, lmin, 16));
            lmin = fminf(lmin, __shfl_xor_sync(0xffffffffu, lmin, 8));
            lmin = fminf(lmin, __shfl_xor_sync(0xffffffffu, lmin, 4));
            lmin = fminf(lmin, __shfl_xor_sync(0xffffffffu, lmin, 2));
            lmin = fminf(lmin, __shfl_xor_sync(0xffffffffu, lmin, 1));
            if (lane == 0) {
                s_minb[t] = __float_as_int(lmin);
                int pos = atomicAdd(&s_ucnt, 1);
                s_unres[pos] = t;
            }
        }
    }
    __syncthreads();

    // ---------------- Phase B: flattened straggler segments ---------------
    const int ucnt = s_ucnt;
    if (ucnt > 0) {
        const int nitems = ucnt * NSEG;
        for (int it = warp; it < nitems; it += 8) {
            const int u = it >> 3;
            const int s = it & (NSEG - 1);
            const int t = s_unres[u];
            const float4 ptv = s_ptv[t];

            const int segbase = CHUNK0 + s * SEGLEN;
            float lmin = __int_as_float(s_minb[t]);  // seed with known bound
            for (int off = lane; off < SEGLEN; off += 32) {
                const int idx = segbase + off;
                float2 p = cnb[idx];
                float2 q = cnb[idx - 1];
                int    m = mb[idx];
                bool start = (idx % n_ == 0);
                float ux = start ? 0.0f : p.x - q.x;
                float uy = start ? 1.0f : p.y - q.y;
                float x  = (m == 1) ? INF_F : p.x;

                float dx = x - ptv.x;
                float dy = p.y - ptv.y;
                float d2 = fmaf(dx, dx, dy * dy);
                float dt = fmaf(ux, ptv.z, uy * ptv.w);
                float cr = fmaf(ux, ptv.w, -uy * ptv.z);
                bool aok = (dt >= 0.0f) && (cr * cr <= 3.0f * dt * dt);

                float cd = (d2 <= 4.0f) ? 0.0f : (fast_sqrt(d2) - 2.0f);
                if (aok) {
                    lmin = fminf(lmin, cd);          // cost == cd exactly
                    if (lmin == 0.0f) break;         // global min reached
                } else if (cd < lmin) {              // prune: cost >= cd
                    float a = atan2f(fabsf(cr), dt);
                    lmin = fminf(lmin, cd + fmaxf(a - YAW_THRESH, 0.0f));
                }
            }
            lmin = fminf(lmin, __shfl_xor_sync(0xffffffffu, lmin, 16));
            lmin = fminf(lmin, __shfl_xor_sync(0xffffffffu, lmin, 8));
            lmin = fminf(lmin, __shfl_xor_sync(0xffffffffu, lmin, 4));
            lmin = fminf(lmin, __shfl_xor_sync(0xffffffffu, lmin, 2));
            lmin = fminf(lmin, __shfl_xor_sync(0xffffffffu, lmin, 1));
            // nonneg floats: int-bit order == value order -> deterministic
            if (lane == 0) atomicMin(&s_minb[t], __float_as_int(lmin));
        }
        __syncthreads();
    }

    // ---------------- Sum over T (deterministic shfl tree) ----------------
    if (tid < 32) {
        float v = __int_as_float(s_minb[tid]);   // t >= 30 slots hold 0
        v += __shfl_xor_sync(0xffffffffu, v, 16);
        v += __shfl_xor_sync(0xffffffffu, v, 8);
        v += __shfl_xor_sync(0xffffffffu, v, 4);
        v += __shfl_xor_sync(0xffffffffu, v, 2);
        v += __shfl_xor_sync(0xffffffffu, v, 1);
        if (tid == 0) out[bk] = v;
    }
}

extern "C" void kernel_launch(void* const* d_in, const int* in_sizes, int n_in,
                              void* d_out, int out_size) {
    const float* preds = (const float*)d_in[0];
    const float* cn    = (const float*)d_in[1];
    const int*   mask  = (const int*)d_in[2];
    float* out = (float*)d_out;

    consistency_kernel<<<BK, BLOCK>>>(preds, cn, mask, out);
}